// round 1
// baseline (speedup 1.0000x reference)
#include <cuda_runtime.h>
#include <math.h>
#include <stdint.h>

#define N_ROWS 131072
#define DIM    512
#define NGRP   4096
#define EPSV   1e-12f

// ---------------- scratch (static device arrays; no allocation allowed) ----------------
__device__ float g_logits[(size_t)N_ROWS * DIM];   // 256 MiB
__device__ float g_feats [(size_t)N_ROWS * DIM];   // 256 MiB
__device__ float g_y     [NGRP * DIM];             // 8 MiB
__device__ float g_outg  [NGRP * DIM];             // 8 MiB
__device__ int   g_counts [NGRP];
__device__ int   g_offsets[NGRP + 1];
__device__ int   g_cursor [NGRP];
__device__ int   g_perm   [N_ROWS];

// ---------------- counting sort of jx ----------------
__global__ void zero_counts_k() {
    int i = blockIdx.x * blockDim.x + threadIdx.x;
    if (i < NGRP) g_counts[i] = 0;
}

__global__ void hist_k(const int* __restrict__ jx) {
    int i = blockIdx.x * blockDim.x + threadIdx.x;
    if (i < N_ROWS) atomicAdd(&g_counts[jx[i]], 1);
}

// single-block exclusive scan over NGRP=4096 counts (1024 threads, 4 elems/thread)
__global__ void scan_k() {
    __shared__ int s[NGRP];
    __shared__ int ps[1024];
    int t = threadIdx.x;
    for (int i = t; i < NGRP; i += 1024) s[i] = g_counts[i];
    __syncthreads();
    int b = t * 4;
    int v0 = s[b], v1 = s[b + 1], v2 = s[b + 2], v3 = s[b + 3];
    int sum = v0 + v1 + v2 + v3;
    ps[t] = sum;
    __syncthreads();
    #pragma unroll
    for (int off = 1; off < 1024; off <<= 1) {
        int x = (t >= off) ? ps[t - off] : 0;
        __syncthreads();
        ps[t] += x;
        __syncthreads();
    }
    int excl = ps[t] - sum;
    int o0 = excl, o1 = o0 + v0, o2 = o1 + v1, o3 = o2 + v2;
    g_offsets[b] = o0;     g_offsets[b + 1] = o1;
    g_offsets[b + 2] = o2; g_offsets[b + 3] = o3;
    g_cursor[b] = o0;      g_cursor[b + 1] = o1;
    g_cursor[b + 2] = o2;  g_cursor[b + 3] = o3;
    if (t == 1023) g_offsets[NGRP] = o3 + v3;
}

__global__ void scatter_k(const int* __restrict__ jx) {
    int i = blockIdx.x * blockDim.x + threadIdx.x;
    if (i < N_ROWS) {
        int g = jx[i];
        int pos = atomicAdd(&g_cursor[g], 1);
        g_perm[pos] = i;
    }
}

// ---------------- fp32 tiled NT GEMM: C[M,Nc] = A[M,K] * B[Nc,K]^T + bias ----------------
// mode 0: A=x,  B=Wg -> g_logits
// mode 1: A=x,  B=Wf -> g_feats
// mode 2: A=g_y, B=Wh -> g_outg
__global__ __launch_bounds__(256, 2) void gemm_nt_k(
    const float* __restrict__ A_in, const float* __restrict__ B,
    const float* __restrict__ bias, int M, int Nc, int K, int mode)
{
    __shared__ float As[8][128];
    __shared__ float Bs[8][128];

    const float* A = (mode == 2) ? (const float*)g_y : A_in;
    float* C = (mode == 0) ? g_logits : (mode == 1) ? g_feats : g_outg;

    const int t  = threadIdx.x;
    const int tx = t & 15;       // col micro-tile index (0..15)
    const int ty = t >> 4;       // row micro-tile index (0..15)
    const int row0 = blockIdx.y * 128;
    const int col0 = blockIdx.x * 128;

    const int lr = t >> 1;           // 0..127 tile row for loads
    const int lk = (t & 1) * 4;      // 0 or 4
    const float* Ap = A + (size_t)(row0 + lr) * K + lk;
    const float* Bp = B + (size_t)(col0 + lr) * K + lk;

    float acc[8][8];
    #pragma unroll
    for (int i = 0; i < 8; i++)
        #pragma unroll
        for (int j = 0; j < 8; j++) acc[i][j] = 0.f;

    for (int k0 = 0; k0 < K; k0 += 8) {
        float4 av = *(const float4*)(Ap + k0);
        float4 bv = *(const float4*)(Bp + k0);
        __syncthreads();
        As[lk + 0][lr] = av.x; As[lk + 1][lr] = av.y;
        As[lk + 2][lr] = av.z; As[lk + 3][lr] = av.w;
        Bs[lk + 0][lr] = bv.x; Bs[lk + 1][lr] = bv.y;
        Bs[lk + 2][lr] = bv.z; Bs[lk + 3][lr] = bv.w;
        __syncthreads();
        #pragma unroll
        for (int k = 0; k < 8; k++) {
            float a[8], bb[8];
            #pragma unroll
            for (int i = 0; i < 8; i++) a[i] = As[k][ty * 8 + i];
            #pragma unroll
            for (int j = 0; j < 8; j++) bb[j] = Bs[k][tx * 8 + j];
            #pragma unroll
            for (int i = 0; i < 8; i++)
                #pragma unroll
                for (int j = 0; j < 8; j++)
                    acc[i][j] = fmaf(a[i], bb[j], acc[i][j]);
        }
    }

    float4 bs0 = *(const float4*)(bias + col0 + tx * 8);
    float4 bs1 = *(const float4*)(bias + col0 + tx * 8 + 4);
    #pragma unroll
    for (int i = 0; i < 8; i++) {
        float* Cp = C + (size_t)(row0 + ty * 8 + i) * Nc + col0 + tx * 8;
        float4 r0 = make_float4(acc[i][0] + bs0.x, acc[i][1] + bs0.y,
                                acc[i][2] + bs0.z, acc[i][3] + bs0.w);
        float4 r1 = make_float4(acc[i][4] + bs1.x, acc[i][5] + bs1.y,
                                acc[i][6] + bs1.z, acc[i][7] + bs1.w);
        *(float4*)Cp       = r0;
        *(float4*)(Cp + 4) = r1;
    }
}

// ---------------- per-group online softmax aggregation (atomic-free) ----------------
// one block per group, one thread per column d
__global__ __launch_bounds__(512) void group_softmax_k() {
    int g = blockIdx.x;
    int d = threadIdx.x;
    int s = g_offsets[g];
    int e = g_offsets[g + 1];
    float m = -INFINITY, num = 0.f, den = 0.f;
    for (int r = s; r < e; r++) {
        int i = g_perm[r];
        float l = g_logits[(size_t)i * DIM + d];
        float f = g_feats [(size_t)i * DIM + d];
        float mn = fmaxf(m, l);
        float al = __expf(m - mn);   // 0 when m=-inf
        float p  = __expf(l - mn);
        num = num * al + f * p;
        den = den * al + p;
        m = mn;
    }
    g_y[g * DIM + d] = num / (den + EPSV);
}

// ---------------- final gather: out[i,:] = outg[jx[i],:] ----------------
__global__ void gather_k(const int* __restrict__ jx, float4* __restrict__ out) {
    int idx = blockIdx.x * blockDim.x + threadIdx.x;   // over N_ROWS * 128 float4s
    if (idx < N_ROWS * (DIM / 4)) {
        int i = idx >> 7;
        int c = idx & 127;
        out[idx] = ((const float4*)g_outg)[((size_t)jx[i] << 7) + c];
    }
}

extern "C" void kernel_launch(void* const* d_in, const int* in_sizes, int n_in,
                              void* d_out, int out_size) {
    const float* x  = (const float*)d_in[0];
    const float* Wf = (const float*)d_in[1];
    const float* bf = (const float*)d_in[2];
    const float* Wg = (const float*)d_in[3];
    const float* bg = (const float*)d_in[4];
    const float* Wh = (const float*)d_in[5];
    const float* bh = (const float*)d_in[6];
    const int*   jx = (const int*)d_in[7];
    float* out = (float*)d_out;
    (void)in_sizes; (void)n_in; (void)out_size;

    // counting sort of jx into g_perm
    zero_counts_k<<<(NGRP + 255) / 256, 256>>>();
    hist_k<<<(N_ROWS + 255) / 256, 256>>>(jx);
    scan_k<<<1, 1024>>>();
    scatter_k<<<(N_ROWS + 255) / 256, 256>>>(jx);

    // logits = x @ Wg^T + bg ; feats = x @ Wf^T + bf
    dim3 g1(DIM / 128, N_ROWS / 128);
    gemm_nt_k<<<g1, 256>>>(x, Wg, bg, N_ROWS, DIM, DIM, 0);
    gemm_nt_k<<<g1, 256>>>(x, Wf, bf, N_ROWS, DIM, DIM, 1);

    // per-group softmax-weighted aggregation -> g_y
    group_softmax_k<<<NGRP, 512>>>();

    // out_group = y @ Wh^T + bh
    dim3 g2(DIM / 128, NGRP / 128);
    gemm_nt_k<<<g2, 256>>>(nullptr, Wh, bh, NGRP, DIM, DIM, 2);

    // out = out_group[jx]
    gather_k<<<(N_ROWS * (DIM / 4) + 255) / 256, 256>>>(jx, (float4*)out);
}

// round 6
// speedup vs baseline: 3.2090x; 3.2090x over previous
#include <cuda_runtime.h>
#include <math.h>
#include <stdint.h>

#define N_ROWS 131072
#define DIM    512
#define NGRP   4096
#define EPSV   1e-12f

// ---------------- scratch (static device arrays; no allocation allowed) ----------------
__device__ float g_xc    [(size_t)N_ROWS * DIM];   // 256 MiB  tf32-rounded x
__device__ float g_logits[(size_t)N_ROWS * DIM];   // 256 MiB
__device__ float g_feats [(size_t)N_ROWS * DIM];   // 256 MiB
__device__ float g_wc    [3][DIM * DIM];           // tf32-rounded Wg, Wf, Wh
__device__ float g_y     [NGRP * DIM];             // tf32-rounded aggregate
__device__ float g_outg  [NGRP * DIM];
__device__ int   g_counts [NGRP];
__device__ int   g_offsets[NGRP + 1];
__device__ int   g_cursor [NGRP];
__device__ int   g_perm   [N_ROWS];

// ====================== helpers ======================
__device__ __forceinline__ uint32_t smem_u32(const void* p) {
    uint32_t a;
    asm("{ .reg .u64 t; cvta.to.shared.u64 t, %1; cvt.u32.u64 %0, t; }" : "=r"(a) : "l"(p));
    return a;
}
__device__ __forceinline__ void cpa16(uint32_t dst, const void* src) {
    asm volatile("cp.async.cg.shared.global [%0], [%1], 16;" :: "r"(dst), "l"(src) : "memory");
}
__device__ __forceinline__ float tf32r(float x) {
    uint32_t u;
    asm("cvt.rna.tf32.f32 %0, %1;" : "=r"(u) : "f"(x));
    return __uint_as_float(u);
}
__device__ __forceinline__ void mma8(float* d, const uint32_t* a, uint32_t b0, uint32_t b1) {
    asm volatile(
        "mma.sync.aligned.m16n8k8.row.col.f32.tf32.tf32.f32 "
        "{%0,%1,%2,%3}, {%4,%5,%6,%7}, {%8,%9}, {%0,%1,%2,%3};"
        : "+f"(d[0]), "+f"(d[1]), "+f"(d[2]), "+f"(d[3])
        : "r"(a[0]), "r"(a[1]), "r"(a[2]), "r"(a[3]), "r"(b0), "r"(b1));
}

// ====================== tf32 mma.sync NT GEMM ======================
// C[M,512] = A[M,512] @ W[512,512]^T + bias
#define KC      32
#define CHUNKS  (DIM / KC)          // 16
#define STAGES  3
#define SA      36                  // floats per smem row (KC + 4 pad)
#define TILE_F  (128 * SA)          // 4608 floats per tile
#define STAGE_F (2 * TILE_F)        // A + B per stage
#define SMEM_B  (STAGES * STAGE_F * 4)   // 110592 bytes

// 128 rows x KC floats, rows stride DIM in gmem, SA in smem (16B segments)
__device__ __forceinline__ void load_tile(uint32_t dst, const float* src, int k0, int t) {
    #pragma unroll
    for (int j = 0; j < 4; j++) {
        int idx = j * 256 + t;
        int row = idx >> 3, seg = idx & 7;
        cpa16(dst + row * (SA * 4) + seg * 16,
              src + (size_t)row * DIM + k0 + seg * 4);
    }
}

// mode 0: grid (8, M/128): blockIdx.x = mat*4 + coltile; A=g_xc; mat0->Wg->g_logits, mat1->Wf->g_feats
// mode 2: grid (4, 32):    A=g_y; W=g_wc[2]; C=g_outg
__global__ __launch_bounds__(256, 2) void gemm_mma(
    int mode, const float* __restrict__ bias0, const float* __restrict__ bias1)
{
    extern __shared__ float sm[];
    const uint32_t sb = smem_u32(sm);
    const int t = threadIdx.x;
    const int wid = t >> 5, lid = t & 31;
    const int g = lid >> 2, c = lid & 3;
    const int wr = wid & 3, wc = wid >> 2;

    const float* A; const float* W; const float* bias; float* C;
    int m0, n0;
    if (mode == 0) {
        int mat = blockIdx.x >> 2, ct = blockIdx.x & 3;
        m0 = blockIdx.y * 128; n0 = ct * 128;
        A = g_xc; W = g_wc[mat];
        bias = mat ? bias1 : bias0;
        C = mat ? g_feats : g_logits;
    } else {
        m0 = blockIdx.y * 128; n0 = blockIdx.x * 128;
        A = g_y; W = g_wc[2]; bias = bias0; C = g_outg;
    }
    const float* Ab = A + (size_t)m0 * DIM;
    const float* Wb = W + (size_t)n0 * DIM;

    float acc[2][8][4];
    #pragma unroll
    for (int mf = 0; mf < 2; mf++)
        #pragma unroll
        for (int nf = 0; nf < 8; nf++)
            #pragma unroll
            for (int q = 0; q < 4; q++) acc[mf][nf][q] = 0.f;

    // prologue: stages 0..STAGES-2
    #pragma unroll
    for (int cc = 0; cc < STAGES - 1; cc++) {
        load_tile(sb + cc * STAGE_F * 4,              Ab, cc * KC, t);
        load_tile(sb + cc * STAGE_F * 4 + TILE_F * 4, Wb, cc * KC, t);
        asm volatile("cp.async.commit_group;" ::: "memory");
    }

    for (int i = 0; i < CHUNKS; i++) {
        asm volatile("cp.async.wait_group 1;" ::: "memory");
        __syncthreads();
        int nxt = i + STAGES - 1;
        if (nxt < CHUNKS) {
            int s = nxt % STAGES;
            load_tile(sb + s * STAGE_F * 4,              Ab, nxt * KC, t);
            load_tile(sb + s * STAGE_F * 4 + TILE_F * 4, Wb, nxt * KC, t);
        }
        asm volatile("cp.async.commit_group;" ::: "memory");

        const float* As = sm + (i % STAGES) * STAGE_F + (wr * 32) * SA;
        const float* Bs = sm + (i % STAGES) * STAGE_F + TILE_F + (wc * 64) * SA;
        #pragma unroll
        for (int kk = 0; kk < KC; kk += 8) {
            uint32_t a[2][4];
            #pragma unroll
            for (int mf = 0; mf < 2; mf++) {
                const float* ap = As + (mf * 16 + g) * SA + kk + c;
                a[mf][0] = __float_as_uint(ap[0]);
                a[mf][1] = __float_as_uint(ap[8 * SA]);
                a[mf][2] = __float_as_uint(ap[4]);
                a[mf][3] = __float_as_uint(ap[8 * SA + 4]);
            }
            #pragma unroll
            for (int nf = 0; nf < 8; nf++) {
                const float* bp = Bs + (nf * 8 + g) * SA + kk + c;
                uint32_t bb0 = __float_as_uint(bp[0]);
                uint32_t bb1 = __float_as_uint(bp[4]);
                mma8(acc[0][nf], a[0], bb0, bb1);
                mma8(acc[1][nf], a[1], bb0, bb1);
            }
        }
    }

    // epilogue
    const int rowb = m0 + wr * 32 + g;
    const int colb = n0 + wc * 64 + c * 2;
    #pragma unroll
    for (int nf = 0; nf < 8; nf++) {
        int col = colb + nf * 8;
        float bv0 = bias[col], bv1 = bias[col + 1];
        #pragma unroll
        for (int mf = 0; mf < 2; mf++) {
            int r0 = rowb + mf * 16;
            float2 v;
            v.x = acc[mf][nf][0] + bv0; v.y = acc[mf][nf][1] + bv1;
            *(float2*)(C + (size_t)r0 * DIM + col) = v;
            v.x = acc[mf][nf][2] + bv0; v.y = acc[mf][nf][3] + bv1;
            *(float2*)(C + (size_t)(r0 + 8) * DIM + col) = v;
        }
    }
}

// ---------------- tf32 pre-conversion ----------------
__global__ void conv_x_k(const float4* __restrict__ x) {
    int i = blockIdx.x * blockDim.x + threadIdx.x;
    if (i < N_ROWS * (DIM / 4)) {
        float4 v = x[i];
        v.x = tf32r(v.x); v.y = tf32r(v.y); v.z = tf32r(v.z); v.w = tf32r(v.w);
        ((float4*)g_xc)[i] = v;
    }
}
__global__ void conv_w_k(const float4* __restrict__ Wg, const float4* __restrict__ Wf,
                         const float4* __restrict__ Wh) {
    int i = blockIdx.x * blockDim.x + threadIdx.x;
    const int per = DIM * DIM / 4;
    if (i < 3 * per) {
        int mat = i / per, j = i % per;
        const float4* src = (mat == 0) ? Wg : (mat == 1) ? Wf : Wh;
        float4 v = src[j];
        v.x = tf32r(v.x); v.y = tf32r(v.y); v.z = tf32r(v.z); v.w = tf32r(v.w);
        ((float4*)g_wc[mat])[j] = v;
    }
}

// ---------------- counting sort of jx ----------------
__global__ void zero_counts_k() {
    int i = blockIdx.x * blockDim.x + threadIdx.x;
    if (i < NGRP) g_counts[i] = 0;
}
__global__ void hist_k(const int* __restrict__ jx) {
    int i = blockIdx.x * blockDim.x + threadIdx.x;
    if (i < N_ROWS) atomicAdd(&g_counts[jx[i]], 1);
}
__global__ void scan_k() {
    __shared__ int s[NGRP];
    __shared__ int ps[1024];
    int t = threadIdx.x;
    for (int i = t; i < NGRP; i += 1024) s[i] = g_counts[i];
    __syncthreads();
    int b = t * 4;
    int v0 = s[b], v1 = s[b + 1], v2 = s[b + 2], v3 = s[b + 3];
    int sum = v0 + v1 + v2 + v3;
    ps[t] = sum;
    __syncthreads();
    #pragma unroll
    for (int off = 1; off < 1024; off <<= 1) {
        int x = (t >= off) ? ps[t - off] : 0;
        __syncthreads();
        ps[t] += x;
        __syncthreads();
    }
    int excl = ps[t] - sum;
    int o0 = excl, o1 = o0 + v0, o2 = o1 + v1, o3 = o2 + v2;
    g_offsets[b] = o0;     g_offsets[b + 1] = o1;
    g_offsets[b + 2] = o2; g_offsets[b + 3] = o3;
    g_cursor[b] = o0;      g_cursor[b + 1] = o1;
    g_cursor[b + 2] = o2;  g_cursor[b + 3] = o3;
    if (t == 1023) g_offsets[NGRP] = o3 + v3;
}
__global__ void scatter_k(const int* __restrict__ jx) {
    int i = blockIdx.x * blockDim.x + threadIdx.x;
    if (i < N_ROWS) {
        int g = jx[i];
        int pos = atomicAdd(&g_cursor[g], 1);
        g_perm[pos] = i;
    }
}

// ---------------- per-group online softmax aggregation ----------------
__global__ __launch_bounds__(512) void group_softmax_k() {
    int g = blockIdx.x;
    int d = threadIdx.x;
    int s = g_offsets[g];
    int e = g_offsets[g + 1];
    float m = -INFINITY, num = 0.f, den = 0.f;
    for (int r = s; r < e; r++) {
        int i = g_perm[r];
        float l = g_logits[(size_t)i * DIM + d];
        float f = g_feats [(size_t)i * DIM + d];
        float mn = fmaxf(m, l);
        float al = __expf(m - mn);
        float p  = __expf(l - mn);
        num = num * al + f * p;
        den = den * al + p;
        m = mn;
    }
    g_y[g * DIM + d] = tf32r(num / (den + EPSV));   // pre-rounded for GEMM3
}

// ---------------- final gather: out[i,:] = outg[jx[i],:] ----------------
__global__ void gather_k(const int* __restrict__ jx, float4* __restrict__ out) {
    int idx = blockIdx.x * blockDim.x + threadIdx.x;
    if (idx < N_ROWS * (DIM / 4)) {
        int i = idx >> 7;
        int c = idx & 127;
        out[idx] = ((const float4*)g_outg)[((size_t)jx[i] << 7) + c];
    }
}

extern "C" void kernel_launch(void* const* d_in, const int* in_sizes, int n_in,
                              void* d_out, int out_size) {
    const float* x  = (const float*)d_in[0];
    const float* Wf = (const float*)d_in[1];
    const float* bf = (const float*)d_in[2];
    const float* Wg = (const float*)d_in[3];
    const float* bg = (const float*)d_in[4];
    const float* Wh = (const float*)d_in[5];
    const float* bh = (const float*)d_in[6];
    const int*   jx = (const int*)d_in[7];
    float* out = (float*)d_out;
    (void)in_sizes; (void)n_in; (void)out_size;

    cudaFuncSetAttribute(gemm_mma, cudaFuncAttributeMaxDynamicSharedMemorySize, SMEM_B);

    // tf32 pre-conversion
    conv_x_k<<<(N_ROWS * (DIM / 4) + 255) / 256, 256>>>((const float4*)x);
    conv_w_k<<<(3 * DIM * DIM / 4 + 255) / 256, 256>>>(
        (const float4*)Wg, (const float4*)Wf, (const float4*)Wh);

    // counting sort of jx into g_perm
    zero_counts_k<<<(NGRP + 255) / 256, 256>>>();
    hist_k<<<(N_ROWS + 255) / 256, 256>>>(jx);
    scan_k<<<1, 1024>>>();
    scatter_k<<<(N_ROWS + 255) / 256, 256>>>(jx);

    // fused: logits = x@Wg^T+bg ; feats = x@Wf^T+bf  (tf32 mma.sync)
    gemm_mma<<<dim3(8, N_ROWS / 128), 256, SMEM_B>>>(0, bg, bf);

    // per-group softmax-weighted aggregation -> g_y
    group_softmax_k<<<NGRP, 512>>>();

    // out_group = y @ Wh^T + bh
    gemm_mma<<<dim3(4, NGRP / 128), 256, SMEM_B>>>(2, bh, nullptr);

    // out = out_group[jx]
    gather_k<<<(N_ROWS * (DIM / 4) + 255) / 256, 256>>>(jx, (float4*)out);
}

// round 8
// speedup vs baseline: 3.4193x; 1.0655x over previous
#include <cuda_runtime.h>
#include <math.h>
#include <stdint.h>

#define N_ROWS 131072
#define DIM    512
#define NGRP   4096
#define EPSV   1e-12f

// ---------------- scratch (static device arrays; no allocation allowed) ----------------
__device__ float g_xs    [(size_t)N_ROWS * DIM];   // 256 MiB: tf32-rounded, group-sorted x
__device__ float g_wc    [3][DIM * DIM];           // tf32-rounded Wg, Wf, Wh
__device__ float g_num   [NGRP * DIM];             // segment sums: feats*exp(l)
__device__ float g_den   [NGRP * DIM];             // segment sums: exp(l)
__device__ float g_y     [NGRP * DIM];             // normalized aggregate (tf32-rounded)
__device__ float g_outg  [NGRP * DIM];
__device__ int   g_counts [NGRP];
__device__ int   g_offsets[NGRP + 1];
__device__ int   g_cursor [NGRP];
__device__ int   g_perm   [N_ROWS];
__device__ int   g_gids   [N_ROWS];                // sorted group id per sorted row

// ====================== helpers ======================
__device__ __forceinline__ uint32_t smem_u32(const void* p) {
    uint32_t a;
    asm("{ .reg .u64 t; cvta.to.shared.u64 t, %1; cvt.u32.u64 %0, t; }" : "=r"(a) : "l"(p));
    return a;
}
__device__ __forceinline__ void cpa16(uint32_t dst, const void* src) {
    asm volatile("cp.async.cg.shared.global [%0], [%1], 16;" :: "r"(dst), "l"(src) : "memory");
}
__device__ __forceinline__ float tf32r(float x) {
    uint32_t u;
    asm("cvt.rna.tf32.f32 %0, %1;" : "=r"(u) : "f"(x));
    return __uint_as_float(u);
}
__device__ __forceinline__ void mma8(float* d, const uint32_t* a, uint32_t b0, uint32_t b1) {
    asm volatile(
        "mma.sync.aligned.m16n8k8.row.col.f32.tf32.tf32.f32 "
        "{%0,%1,%2,%3}, {%4,%5,%6,%7}, {%8,%9}, {%0,%1,%2,%3};"
        : "+f"(d[0]), "+f"(d[1]), "+f"(d[2]), "+f"(d[3])
        : "r"(a[0]), "r"(a[1]), "r"(a[2]), "r"(a[3]), "r"(b0), "r"(b1));
}

// ====================== GEMM tiling constants ======================
#define KC      32
#define CHUNKS  (DIM / KC)          // 16
#define STAGES  3
#define SA      36                  // floats per smem row (KC + 4 pad)
#define ATILE_F (128 * SA)          // 4608 floats (A: 128 rows)
#define STAGE_F (256 * SA)          // 9216 floats (A 128 rows + B 128 rows)
#define SMEM_B  (STAGES * STAGE_F * 4)   // 110592 bytes

// 128 rows x KC floats
__device__ __forceinline__ void load_tile_A(uint32_t dst, const float* src, int k0, int t) {
    #pragma unroll
    for (int j = 0; j < 4; j++) {
        int idx = j * 256 + t;
        int row = idx >> 3, seg = idx & 7;
        cpa16(dst + row * (SA * 4) + seg * 16,
              src + (size_t)row * DIM + k0 + seg * 4);
    }
}
// B tile: rows 0..63 from Wg (rows n0..), rows 64..127 from Wf (rows n0..)
__device__ __forceinline__ void load_tile_B2(uint32_t dst, const float* Wg, const float* Wf,
                                             int n0, int k0, int t) {
    #pragma unroll
    for (int j = 0; j < 4; j++) {
        int idx = j * 256 + t;
        int row = idx >> 3, seg = idx & 7;
        const float* base = (row < 64) ? (Wg + (size_t)(n0 + row) * DIM)
                                       : (Wf + (size_t)(n0 + row - 64) * DIM);
        cpa16(dst + row * (SA * 4) + seg * 16, base + k0 + seg * 4);
    }
}

// ====================== fused dual-GEMM + softmax segment-reduce ======================
// grid (8, 1024): n0 = bx*64, m0 = by*128. A = g_xs (sorted rows).
// Computes l = xs@Wg^T+bg, f = xs@Wf^T+bf for the tile, then segmented
// num/den sums over sorted rows into g_num/g_den via atomicAdd.
__global__ __launch_bounds__(256, 2) void gemm_fused(
    const float* __restrict__ bg_, const float* __restrict__ bf_)
{
    extern __shared__ float sm[];
    const uint32_t sb = smem_u32(sm);
    const int t = threadIdx.x;
    const int wid = t >> 5, lid = t & 31;
    const int g = lid >> 2, c = lid & 3;
    const int wr = wid & 3, wc = wid >> 2;

    const int n0 = blockIdx.x * 64;
    const int m0 = blockIdx.y * 128;
    const float* Ab = g_xs + (size_t)m0 * DIM;
    const float* Wg = g_wc[0];
    const float* Wf = g_wc[1];

    float accg[2][4][4], accf[2][4][4];
    #pragma unroll
    for (int mf = 0; mf < 2; mf++)
        #pragma unroll
        for (int nf = 0; nf < 4; nf++)
            #pragma unroll
            for (int q = 0; q < 4; q++) { accg[mf][nf][q] = 0.f; accf[mf][nf][q] = 0.f; }

    #pragma unroll
    for (int cc = 0; cc < STAGES - 1; cc++) {
        load_tile_A(sb + cc * STAGE_F * 4, Ab, cc * KC, t);
        load_tile_B2(sb + cc * STAGE_F * 4 + ATILE_F * 4, Wg, Wf, n0, cc * KC, t);
        asm volatile("cp.async.commit_group;" ::: "memory");
    }

    for (int i = 0; i < CHUNKS; i++) {
        asm volatile("cp.async.wait_group 1;" ::: "memory");
        __syncthreads();
        int nxt = i + STAGES - 1;
        if (nxt < CHUNKS) {
            int s = nxt % STAGES;
            load_tile_A(sb + s * STAGE_F * 4, Ab, nxt * KC, t);
            load_tile_B2(sb + s * STAGE_F * 4 + ATILE_F * 4, Wg, Wf, n0, nxt * KC, t);
        }
        asm volatile("cp.async.commit_group;" ::: "memory");

        const float* As = sm + (i % STAGES) * STAGE_F + (wr * 32) * SA;
        const float* B0 = sm + (i % STAGES) * STAGE_F + ATILE_F + (wc * 32) * SA;
        #pragma unroll
        for (int kk = 0; kk < KC; kk += 8) {
            uint32_t a[2][4];
            #pragma unroll
            for (int mf = 0; mf < 2; mf++) {
                const float* ap = As + (mf * 16 + g) * SA + kk + c;
                a[mf][0] = __float_as_uint(ap[0]);
                a[mf][1] = __float_as_uint(ap[8 * SA]);
                a[mf][2] = __float_as_uint(ap[4]);
                a[mf][3] = __float_as_uint(ap[8 * SA + 4]);
            }
            #pragma unroll
            for (int nf = 0; nf < 4; nf++) {
                const float* bp0 = B0 + (nf * 8 + g) * SA + kk + c;
                uint32_t p0 = __float_as_uint(bp0[0]);
                uint32_t p1 = __float_as_uint(bp0[4]);
                mma8(accg[0][nf], a[0], p0, p1);
                mma8(accg[1][nf], a[1], p0, p1);
                const float* bp1 = bp0 + 64 * SA;
                uint32_t q0 = __float_as_uint(bp1[0]);
                uint32_t q1 = __float_as_uint(bp1[4]);
                mma8(accf[0][nf], a[0], q0, q1);
                mma8(accf[1][nf], a[1], q0, q1);
            }
        }
    }
    __syncthreads();

    // ---- epilogue: stage (l, f) transposed [col][row], stride 133 ----
    float* sl = sm;
    float* sf = sm + 64 * 133;
    int* sgid = (int*)(sm + 2 * 64 * 133);
    if (t < 128) sgid[t] = g_gids[m0 + t];
    #pragma unroll
    for (int nf = 0; nf < 4; nf++) {
        int cb = wc * 32 + nf * 8 + c * 2;
        float2 bgv = *(const float2*)(bg_ + n0 + cb);
        float2 bfv = *(const float2*)(bf_ + n0 + cb);
        #pragma unroll
        for (int mf = 0; mf < 2; mf++) {
            int r0 = wr * 32 + mf * 16 + g;
            sl[cb * 133 + r0]           = accg[mf][nf][0] + bgv.x;
            sl[(cb + 1) * 133 + r0]     = accg[mf][nf][1] + bgv.y;
            sl[cb * 133 + r0 + 8]       = accg[mf][nf][2] + bgv.x;
            sl[(cb + 1) * 133 + r0 + 8] = accg[mf][nf][3] + bgv.y;
            sf[cb * 133 + r0]           = accf[mf][nf][0] + bfv.x;
            sf[(cb + 1) * 133 + r0]     = accf[mf][nf][1] + bfv.y;
            sf[cb * 133 + r0 + 8]       = accf[mf][nf][2] + bfv.x;
            sf[(cb + 1) * 133 + r0 + 8] = accf[mf][nf][3] + bfv.y;
        }
    }
    __syncthreads();

    // ---- segmented reduce over sorted rows; flush per group via atomics ----
    {
        int col = t & 63, q = t >> 6;
        int gcol = n0 + col;
        int r = q * 32;
        int curg = sgid[r];
        float num = 0.f, den = 0.f;
        #pragma unroll 1
        for (int k = 0; k < 32; k++, r++) {
            int gg = sgid[r];
            float l = sl[col * 133 + r];
            float f = sf[col * 133 + r];
            float e = __expf(l);
            if (gg != curg) {
                atomicAdd(&g_num[(size_t)curg * DIM + gcol], num);
                atomicAdd(&g_den[(size_t)curg * DIM + gcol], den);
                num = 0.f; den = 0.f; curg = gg;
            }
            num += f * e;
            den += e;
        }
        atomicAdd(&g_num[(size_t)curg * DIM + gcol], num);
        atomicAdd(&g_den[(size_t)curg * DIM + gcol], den);
    }
}

// ====================== GEMM3: out_group = y @ Wh^T + bh ======================
// grid (4, 32), CTA 128x128, same pipeline as before
__global__ __launch_bounds__(256, 2) void gemm_mma3(const float* __restrict__ bias)
{
    extern __shared__ float sm[];
    const uint32_t sb = smem_u32(sm);
    const int t = threadIdx.x;
    const int wid = t >> 5, lid = t & 31;
    const int g = lid >> 2, c = lid & 3;
    const int wr = wid & 3, wc = wid >> 2;

    const int m0 = blockIdx.y * 128, n0 = blockIdx.x * 128;
    const float* Ab = g_y + (size_t)m0 * DIM;
    const float* Wb = g_wc[2] + (size_t)n0 * DIM;
    float* C = g_outg;

    float acc[2][8][4];
    #pragma unroll
    for (int mf = 0; mf < 2; mf++)
        #pragma unroll
        for (int nf = 0; nf < 8; nf++)
            #pragma unroll
            for (int q = 0; q < 4; q++) acc[mf][nf][q] = 0.f;

    #pragma unroll
    for (int cc = 0; cc < STAGES - 1; cc++) {
        load_tile_A(sb + cc * STAGE_F * 4,               Ab, cc * KC, t);
        load_tile_A(sb + cc * STAGE_F * 4 + ATILE_F * 4, Wb, cc * KC, t);
        asm volatile("cp.async.commit_group;" ::: "memory");
    }

    for (int i = 0; i < CHUNKS; i++) {
        asm volatile("cp.async.wait_group 1;" ::: "memory");
        __syncthreads();
        int nxt = i + STAGES - 1;
        if (nxt < CHUNKS) {
            int s = nxt % STAGES;
            load_tile_A(sb + s * STAGE_F * 4,               Ab, nxt * KC, t);
            load_tile_A(sb + s * STAGE_F * 4 + ATILE_F * 4, Wb, nxt * KC, t);
        }
        asm volatile("cp.async.commit_group;" ::: "memory");

        const float* As = sm + (i % STAGES) * STAGE_F + (wr * 32) * SA;
        const float* Bs = sm + (i % STAGES) * STAGE_F + ATILE_F + (wc * 64) * SA;
        #pragma unroll
        for (int kk = 0; kk < KC; kk += 8) {
            uint32_t a[2][4];
            #pragma unroll
            for (int mf = 0; mf < 2; mf++) {
                const float* ap = As + (mf * 16 + g) * SA + kk + c;
                a[mf][0] = __float_as_uint(ap[0]);
                a[mf][1] = __float_as_uint(ap[8 * SA]);
                a[mf][2] = __float_as_uint(ap[4]);
                a[mf][3] = __float_as_uint(ap[8 * SA + 4]);
            }
            #pragma unroll
            for (int nf = 0; nf < 8; nf++) {
                const float* bp = Bs + (nf * 8 + g) * SA + kk + c;
                uint32_t bb0 = __float_as_uint(bp[0]);
                uint32_t bb1 = __float_as_uint(bp[4]);
                mma8(acc[0][nf], a[0], bb0, bb1);
                mma8(acc[1][nf], a[1], bb0, bb1);
            }
        }
    }

    const int rowb = m0 + wr * 32 + g;
    const int colb = n0 + wc * 64 + c * 2;
    #pragma unroll
    for (int nf = 0; nf < 8; nf++) {
        int col = colb + nf * 8;
        float bv0 = bias[col], bv1 = bias[col + 1];
        #pragma unroll
        for (int mf = 0; mf < 2; mf++) {
            int r0 = rowb + mf * 16;
            float2 v;
            v.x = acc[mf][nf][0] + bv0; v.y = acc[mf][nf][1] + bv1;
            *(float2*)(C + (size_t)r0 * DIM + col) = v;
            v.x = acc[mf][nf][2] + bv0; v.y = acc[mf][nf][3] + bv1;
            *(float2*)(C + (size_t)(r0 + 8) * DIM + col) = v;
        }
    }
}

// ---------------- small kernels ----------------
__global__ void zero_counts_k() {
    int i = blockIdx.x * blockDim.x + threadIdx.x;
    if (i < NGRP) g_counts[i] = 0;
}
__global__ void zero_nd_k() {
    int i = blockIdx.x * blockDim.x + threadIdx.x;
    if (i < NGRP * DIM / 4) {
        float4 z = make_float4(0.f, 0.f, 0.f, 0.f);
        ((float4*)g_num)[i] = z;
        ((float4*)g_den)[i] = z;
    }
}
__global__ void hist_k(const int* __restrict__ jx) {
    int i = blockIdx.x * blockDim.x + threadIdx.x;
    if (i < N_ROWS) atomicAdd(&g_counts[jx[i]], 1);
}
__global__ void scan_k() {
    __shared__ int s[NGRP];
    __shared__ int ps[1024];
    int t = threadIdx.x;
    for (int i = t; i < NGRP; i += 1024) s[i] = g_counts[i];
    __syncthreads();
    int b = t * 4;
    int v0 = s[b], v1 = s[b + 1], v2 = s[b + 2], v3 = s[b + 3];
    int sum = v0 + v1 + v2 + v3;
    ps[t] = sum;
    __syncthreads();
    #pragma unroll
    for (int off = 1; off < 1024; off <<= 1) {
        int x = (t >= off) ? ps[t - off] : 0;
        __syncthreads();
        ps[t] += x;
        __syncthreads();
    }
    int excl = ps[t] - sum;
    int o0 = excl, o1 = o0 + v0, o2 = o1 + v1, o3 = o2 + v2;
    g_offsets[b] = o0;     g_offsets[b + 1] = o1;
    g_offsets[b + 2] = o2; g_offsets[b + 3] = o3;
    g_cursor[b] = o0;      g_cursor[b + 1] = o1;
    g_cursor[b + 2] = o2;  g_cursor[b + 3] = o3;
    if (t == 1023) g_offsets[NGRP] = o3 + v3;
}
__global__ void scatter_k(const int* __restrict__ jx) {
    int i = blockIdx.x * blockDim.x + threadIdx.x;
    if (i < N_ROWS) {
        int g = jx[i];
        int pos = atomicAdd(&g_cursor[g], 1);
        g_perm[pos] = i;
        g_gids[pos] = g;
    }
}

// permuted tf32 convert: g_xs[r] = tf32(x[perm[r]])
__global__ void conv_xs_k(const float4* __restrict__ x) {
    int idx = blockIdx.x * blockDim.x + threadIdx.x;
    if (idx < N_ROWS * (DIM / 4)) {
        int r = idx >> 7, cc = idx & 127;
        int src = g_perm[r];
        float4 v = x[((size_t)src << 7) + cc];
        v.x = tf32r(v.x); v.y = tf32r(v.y); v.z = tf32r(v.z); v.w = tf32r(v.w);
        ((float4*)g_xs)[idx] = v;
    }
}
__global__ void conv_w_k(const float4* __restrict__ Wg, const float4* __restrict__ Wf,
                         const float4* __restrict__ Wh) {
    int i = blockIdx.x * blockDim.x + threadIdx.x;
    const int per = DIM * DIM / 4;
    if (i < 3 * per) {
        int mat = i / per, j = i % per;
        const float4* src = (mat == 0) ? Wg : (mat == 1) ? Wf : Wh;
        float4 v = src[j];
        v.x = tf32r(v.x); v.y = tf32r(v.y); v.z = tf32r(v.z); v.w = tf32r(v.w);
        ((float4*)g_wc[mat])[j] = v;
    }
}

// y = num / (den + eps), tf32-rounded for GEMM3
__global__ void norm_y_k() {
    int i = blockIdx.x * blockDim.x + threadIdx.x;
    if (i < NGRP * DIM) g_y[i] = tf32r(g_num[i] / (g_den[i] + EPSV));
}

// out[i,:] = outg[jx[i],:]
__global__ void gather_k(const int* __restrict__ jx, float4* __restrict__ out) {
    int idx = blockIdx.x * blockDim.x + threadIdx.x;
    if (idx < N_ROWS * (DIM / 4)) {
        int i = idx >> 7;
        int c = idx & 127;
        out[idx] = ((const float4*)g_outg)[((size_t)jx[i] << 7) + c];
    }
}

extern "C" void kernel_launch(void* const* d_in, const int* in_sizes, int n_in,
                              void* d_out, int out_size) {
    const float* x  = (const float*)d_in[0];
    const float* Wf = (const float*)d_in[1];
    const float* bf = (const float*)d_in[2];
    const float* Wg = (const float*)d_in[3];
    const float* bg = (const float*)d_in[4];
    const float* Wh = (const float*)d_in[5];
    const float* bh = (const float*)d_in[6];
    const int*   jx = (const int*)d_in[7];
    float* out = (float*)d_out;
    (void)in_sizes; (void)n_in; (void)out_size;

    cudaFuncSetAttribute(gemm_fused, cudaFuncAttributeMaxDynamicSharedMemorySize, SMEM_B);
    cudaFuncSetAttribute(gemm_mma3,  cudaFuncAttributeMaxDynamicSharedMemorySize, SMEM_B);

    // zero accumulators + counting sort of jx
    zero_counts_k<<<(NGRP + 255) / 256, 256>>>();
    zero_nd_k<<<(NGRP * DIM / 4 + 255) / 256, 256>>>();
    hist_k<<<(N_ROWS + 255) / 256, 256>>>(jx);
    scan_k<<<1, 1024>>>();
    scatter_k<<<(N_ROWS + 255) / 256, 256>>>(jx);

    // tf32 pre-conversion (x permuted into sorted order)
    conv_w_k<<<(3 * DIM * DIM / 4 + 255) / 256, 256>>>(
        (const float4*)Wg, (const float4*)Wf, (const float4*)Wh);
    conv_xs_k<<<(N_ROWS * (DIM / 4) + 255) / 256, 256>>>((const float4*)x);

    // fused dual GEMM + softmax segment-reduce
    gemm_fused<<<dim3(8, N_ROWS / 128), 256, SMEM_B>>>(bg, bf);

    // y = num/(den+eps)
    norm_y_k<<<(NGRP * DIM + 255) / 256, 256>>>();

    // out_group = y @ Wh^T + bh
    gemm_mma3<<<dim3(4, NGRP / 128), 256, SMEM_B>>>(bh);

    // out = out_group[jx]
    gather_k<<<(N_ROWS * (DIM / 4) + 255) / 256, 256>>>(jx, (float4*)out);
}